// round 13
// baseline (speedup 1.0000x reference)
#include <cuda_runtime.h>
#include <cuda_bf16.h>

typedef unsigned long long u64;

// Problem shapes
#define B_   1024
#define L_   200
#define DIM_ 100
#define NP   128               // padded N
#define KSPLIT 16
#define KCHUNK (B_ / KSPLIT)   // 64

// Scratch (allocation-free: __device__ globals)
__device__ __align__(256) float g_rel[B_ * NP];                 // mean-pooled, padded
__device__ __align__(256) float g_tmp[B_ * NP];                 // A @ rel
__device__ __align__(256) float g_part[KSPLIT * B_ * NP];       // split-K partials

// ---------------------------------------------------------------------------
// packed f32x2 helpers (sm_103a)
// ---------------------------------------------------------------------------
__device__ __forceinline__ void fma2(u64& d, u64 a, u64 b) {
    asm("fma.rn.f32x2 %0, %1, %2, %0;" : "+l"(d) : "l"(a), "l"(b));
}
__device__ __forceinline__ u64 pack2(float x) {
    u64 r;
    asm("mov.b64 %0, {%1, %1};" : "=l"(r) : "f"(x));
    return r;
}
__device__ __forceinline__ void unpack2(u64 v, float& lo, float& hi) {
    asm("mov.b64 {%0, %1}, %2;" : "=f"(lo), "=f"(hi) : "l"(v));
}

// ---------------------------------------------------------------------------
// Kernel 1: gather + mean-pool.  rel[b][t] = (1/len[b]) * sum_l emb[items[b,l]][t]
// 256 threads: warp w handles rows l in [w*25, w*25+25); lanes 0..24 each own
// one float4 column segment (25*4 = 100). emb rows are 400B -> 16B aligned.
// ---------------------------------------------------------------------------
__global__ __launch_bounds__(256) void gather_kernel(const float* __restrict__ emb,
                                                     const int* __restrict__ items,
                                                     const float* __restrict__ slen) {
    int b = blockIdx.x;
    int t = threadIdx.x;
    int w = t >> 5;              // warp 0..7
    int c = t & 31;              // lane

    __shared__ int sidx[L_];
    __shared__ float spart[8][DIM_];

    for (int l = t; l < L_; l += 256) sidx[l] = items[b * L_ + l];
    __syncthreads();

    float4 acc = make_float4(0.f, 0.f, 0.f, 0.f);
    if (c < 25) {
        int l0 = w * 25;
        #pragma unroll 5
        for (int l = l0; l < l0 + 25; l++) {
            int j = sidx[l];
            if (j > 0) {
                float4 v = *(const float4*)&emb[(long long)(j - 1) * DIM_ + c * 4];
                acc.x += v.x; acc.y += v.y; acc.z += v.z; acc.w += v.w;
            }
        }
        spart[w][c * 4 + 0] = acc.x;
        spart[w][c * 4 + 1] = acc.y;
        spart[w][c * 4 + 2] = acc.z;
        spart[w][c * 4 + 3] = acc.w;
    }
    __syncthreads();

    if (t < NP) {
        float s = 0.f;
        if (t < DIM_) {
            #pragma unroll
            for (int ww = 0; ww < 8; ww++) s += spart[ww][t];
            s *= 1.f / slen[b];
        }
        g_rel[b * NP + t] = s;
    }
}

// ---------------------------------------------------------------------------
// Kernel 2: split-K SGEMM, f32x2, 8m x 8n per thread.
// BM=64, BN=128, BK=16, KCHUNK=64, grid (16,16)=256 blocks, 128 threads,
// double-buffered, 3 CTAs/SM.
// Warp ty owns m rows [ty*16, ty*16+16); lane: lm=lid>>4 picks 8-row half,
// ln=lid&15 picks cols {ln*4..+4} u {64+ln*4..+4} (conflict-free stride-16B).
// ---------------------------------------------------------------------------
__global__ __launch_bounds__(128, 3) void gemm_splitk(const float* __restrict__ A,
                                                      int selB) {
    const float* __restrict__ Bm = selB ? g_tmp : g_rel;
    __shared__ float As[2][16][64];      // [k][m], m contiguous -> free m-pairs
    __shared__ float Bs[2][16][NP];

    int tid = threadIdx.x;
    int ty  = tid >> 5;          // warp 0..3
    int lid = tid & 31;
    int lm  = lid >> 4;          // 0..1
    int ln  = lid & 15;          // 0..15
    int m0 = blockIdx.x * 64;
    int kbase = blockIdx.y * KCHUNK;
    int mt = ty * 16 + lm * 8;   // thread m base in tile
    int nt = ln * 4;             // thread n base (plus +64 second chunk)

    // load-index decomposition
    int ar = tid >> 1;           // A row 0..63
    int ak = (tid & 1) * 8;      // A k base: 0 or 8
    int br = tid >> 3;           // B row 0..15
    int bc = (tid & 7) * 16;     // B col base 0..112

    const float* Arow = &A[(size_t)(m0 + ar) * B_ + kbase + ak];
    const float* Brow = &Bm[(size_t)(kbase + br) * NP + bc];

    // prologue: stage 0 -> buffer 0
    {
        float4 a0 = *(const float4*)&Arow[0];
        float4 a1 = *(const float4*)&Arow[4];
        As[0][ak + 0][ar] = a0.x; As[0][ak + 1][ar] = a0.y;
        As[0][ak + 2][ar] = a0.z; As[0][ak + 3][ar] = a0.w;
        As[0][ak + 4][ar] = a1.x; As[0][ak + 5][ar] = a1.y;
        As[0][ak + 6][ar] = a1.z; As[0][ak + 7][ar] = a1.w;
        #pragma unroll
        for (int j = 0; j < 4; j++)
            *(float4*)&Bs[0][br][bc + j * 4] = *(const float4*)&Brow[j * 4];
    }
    __syncthreads();

    u64 acc2[4][8];              // [m-pair][n]; n 0-3 = cols nt+j, 4-7 = cols nt+64+j
    #pragma unroll
    for (int i = 0; i < 4; i++)
        #pragma unroll
        for (int j = 0; j < 8; j++) acc2[i][j] = 0ULL;

    const int T = KCHUNK / 16;   // 4 steps
    #pragma unroll
    for (int s = 0; s < T; s++) {
        float4 a0p, a1p, bp0, bp1, bp2, bp3;
        if (s + 1 < T) {
            int ko = (s + 1) * 16;
            a0p = *(const float4*)&Arow[ko];
            a1p = *(const float4*)&Arow[ko + 4];
            bp0 = *(const float4*)&Brow[(size_t)ko * NP + 0];
            bp1 = *(const float4*)&Brow[(size_t)ko * NP + 4];
            bp2 = *(const float4*)&Brow[(size_t)ko * NP + 8];
            bp3 = *(const float4*)&Brow[(size_t)ko * NP + 12];
        }
        int cb = s & 1;
        #pragma unroll
        for (int k = 0; k < 16; k++) {
            ulonglong2 p0 = *(const ulonglong2*)&As[cb][k][mt];      // m-pairs 0,1
            ulonglong2 p1 = *(const ulonglong2*)&As[cb][k][mt + 4];  // m-pairs 2,3
            float4 bv0 = *(const float4*)&Bs[cb][k][nt];             // cols nt..nt+3
            float4 bv1 = *(const float4*)&Bs[cb][k][nt + 64];        // cols nt+64..+67
            u64 a2[4] = {p0.x, p0.y, p1.x, p1.y};
            u64 b2[8] = {pack2(bv0.x), pack2(bv0.y), pack2(bv0.z), pack2(bv0.w),
                         pack2(bv1.x), pack2(bv1.y), pack2(bv1.z), pack2(bv1.w)};
            #pragma unroll
            for (int i = 0; i < 4; i++)
                #pragma unroll
                for (int j = 0; j < 8; j++)
                    fma2(acc2[i][j], a2[i], b2[j]);
        }
        if (s + 1 < T) {
            int nb = cb ^ 1;
            As[nb][ak + 0][ar] = a0p.x; As[nb][ak + 1][ar] = a0p.y;
            As[nb][ak + 2][ar] = a0p.z; As[nb][ak + 3][ar] = a0p.w;
            As[nb][ak + 4][ar] = a1p.x; As[nb][ak + 5][ar] = a1p.y;
            As[nb][ak + 6][ar] = a1p.z; As[nb][ak + 7][ar] = a1p.w;
            *(float4*)&Bs[nb][br][bc + 0]  = bp0;
            *(float4*)&Bs[nb][br][bc + 4]  = bp1;
            *(float4*)&Bs[nb][br][bc + 8]  = bp2;
            *(float4*)&Bs[nb][br][bc + 12] = bp3;
            __syncthreads();
        }
    }

    // unpack + write partials
    float* P = g_part + (size_t)blockIdx.y * (B_ * NP);
    #pragma unroll
    for (int i = 0; i < 4; i++) {
        float r0[8], r1[8];
        #pragma unroll
        for (int j = 0; j < 8; j++) unpack2(acc2[i][j], r0[j], r1[j]);
        int m = m0 + mt + 2 * i;
        *(float4*)&P[(size_t)m * NP + nt]            = make_float4(r0[0], r0[1], r0[2], r0[3]);
        *(float4*)&P[(size_t)m * NP + nt + 64]       = make_float4(r0[4], r0[5], r0[6], r0[7]);
        *(float4*)&P[(size_t)(m + 1) * NP + nt]      = make_float4(r1[0], r1[1], r1[2], r1[3]);
        *(float4*)&P[(size_t)(m + 1) * NP + nt + 64] = make_float4(r1[4], r1[5], r1[6], r1[7]);
    }
}

// ---------------------------------------------------------------------------
// Kernel 3: reduce split-K partials into g_tmp (float4 vectorized)
// ---------------------------------------------------------------------------
__global__ void reduce_kernel() {
    int i = (blockIdx.x * 256 + threadIdx.x) * 4;   // 0 .. 131068
    float4 s = make_float4(0.f, 0.f, 0.f, 0.f);
    #pragma unroll
    for (int c = 0; c < KSPLIT; c++) {
        float4 v = *(const float4*)&g_part[c * (B_ * NP) + i];
        s.x += v.x; s.y += v.y; s.z += v.z; s.w += v.w;
    }
    *(float4*)&g_tmp[i] = s;
}

// ---------------------------------------------------------------------------
// Kernel 4: fused split-K reduce + SELU + L2 row-normalize -> out [1024,100]
// ---------------------------------------------------------------------------
__global__ void epilogue_kernel(float* __restrict__ out) {
    int b = blockIdx.x;
    int t = threadIdx.x;

    float s = 0.f;
    #pragma unroll
    for (int c = 0; c < KSPLIT; c++) s += g_part[c * (B_ * NP) + b * NP + t];

    const float kScale = 1.0507009873554804934193349852946f;
    const float kAlpha = 1.6732632423543772848170429916717f;
    float cv = kScale * (s > 0.f ? s : kAlpha * (expf(s) - 1.f));

    float v = (t < DIM_) ? cv * cv : 0.f;
    #pragma unroll
    for (int o = 16; o > 0; o >>= 1) v += __shfl_xor_sync(0xFFFFFFFFu, v, o);
    __shared__ float red[4];
    if ((t & 31) == 0) red[t >> 5] = v;
    __syncthreads();
    float nrm = rsqrtf(red[0] + red[1] + red[2] + red[3]);

    if (t < DIM_) out[b * DIM_ + t] = cv * nrm;
}

// ---------------------------------------------------------------------------
extern "C" void kernel_launch(void* const* d_in, const int* in_sizes, int n_in,
                              void* d_out, int out_size) {
    const float* emb   = (const float*)d_in[0];      // [50000,100] f32
    const int*   items = (const int*)d_in[1];        // [1024,200] int32
    const float* A     = (const float*)d_in[2];      // [1024,1024] f32
    const float* D     = (const float*)d_in[3];      // [1024,1024] f32
    const float* slen  = (const float*)d_in[4];      // [1024,1] f32
    float*       out   = (float*)d_out;              // [1024,100] f32

    gather_kernel<<<B_, 256>>>(emb, items, slen);

    dim3 ggrid(B_ / 64, KSPLIT);                  // (16,16) = 256 blocks
    gemm_splitk<<<ggrid, 128>>>(A, /*selB=*/0);   // partials of A @ rel
    reduce_kernel<<<(B_ * NP) / 1024, 256>>>();   // g_tmp = A @ rel
    gemm_splitk<<<ggrid, 128>>>(D, /*selB=*/1);   // partials of D @ (A @ rel)
    epilogue_kernel<<<B_, 128>>>(out);            // reduce + selu + L2 norm
}

// round 14
// speedup vs baseline: 1.1487x; 1.1487x over previous
#include <cuda_runtime.h>
#include <cuda_bf16.h>

typedef unsigned long long u64;

// Problem shapes
#define B_   1024
#define L_   200
#define DIM_ 100
#define NP   128               // padded N
#define KSPLIT 16
#define KCHUNK (B_ / KSPLIT)   // 64

// Scratch (allocation-free: __device__ globals)
__device__ __align__(256) float g_rel[B_ * NP];                 // mean-pooled, padded
__device__ __align__(256) float g_tmp[B_ * NP];                 // A @ rel
__device__ __align__(256) float g_part[KSPLIT * B_ * NP];       // split-K partials

// ---------------------------------------------------------------------------
// packed f32x2 helpers (sm_103a)
// ---------------------------------------------------------------------------
__device__ __forceinline__ void fma2(u64& d, u64 a, u64 b) {
    asm("fma.rn.f32x2 %0, %1, %2, %0;" : "+l"(d) : "l"(a), "l"(b));
}
__device__ __forceinline__ u64 pack2(float x) {
    u64 r;
    asm("mov.b64 %0, {%1, %1};" : "=l"(r) : "f"(x));
    return r;
}
__device__ __forceinline__ void unpack2(u64 v, float& lo, float& hi) {
    asm("mov.b64 {%0, %1}, %2;" : "=f"(lo), "=f"(hi) : "l"(v));
}

// ---------------------------------------------------------------------------
// Kernel 1: gather + mean-pool.  rel[b][t] = (1/len[b]) * sum_l emb[items[b,l]][t]
// 256 threads: warp w handles rows l in [w*25, w*25+25); lanes 0..24 each own
// one float4 column segment (25*4 = 100). emb rows are 400B -> 16B aligned.
// ---------------------------------------------------------------------------
__global__ __launch_bounds__(256) void gather_kernel(const float* __restrict__ emb,
                                                     const int* __restrict__ items,
                                                     const float* __restrict__ slen) {
    int b = blockIdx.x;
    int t = threadIdx.x;
    int w = t >> 5;              // warp 0..7
    int c = t & 31;              // lane

    __shared__ int sidx[L_];
    __shared__ float spart[8][DIM_];

    for (int l = t; l < L_; l += 256) sidx[l] = items[b * L_ + l];
    __syncthreads();

    float4 acc = make_float4(0.f, 0.f, 0.f, 0.f);
    if (c < 25) {
        int l0 = w * 25;
        #pragma unroll 5
        for (int l = l0; l < l0 + 25; l++) {
            int j = sidx[l];
            if (j > 0) {
                float4 v = *(const float4*)&emb[(long long)(j - 1) * DIM_ + c * 4];
                acc.x += v.x; acc.y += v.y; acc.z += v.z; acc.w += v.w;
            }
        }
        spart[w][c * 4 + 0] = acc.x;
        spart[w][c * 4 + 1] = acc.y;
        spart[w][c * 4 + 2] = acc.z;
        spart[w][c * 4 + 3] = acc.w;
    }
    __syncthreads();

    if (t < NP) {
        float s = 0.f;
        if (t < DIM_) {
            #pragma unroll
            for (int ww = 0; ww < 8; ww++) s += spart[ww][t];
            s *= 1.f / slen[b];
        }
        g_rel[b * NP + t] = s;
    }
}

// ---------------------------------------------------------------------------
// Kernel 2: split-K SGEMM, f32x2, 8m x 4n per thread (round-4 proven shape)
// + register-level software pipelining of the inner k loop.
// BM=64, BN=128, BK=16, KCHUNK=64, grid (16,16)=256 blocks, 256 threads,
// smem double-buffered.
// warp ty owns rows [ty*8, ty*8+8) (4 m-pairs), lane tx owns cols [tx*4,+4).
// ---------------------------------------------------------------------------
__global__ __launch_bounds__(256, 2) void gemm_splitk(const float* __restrict__ A,
                                                      int selB) {
    const float* __restrict__ Bm = selB ? g_tmp : g_rel;
    __shared__ float As[2][16][64];      // [k][m], m contiguous -> free m-pairs
    __shared__ float Bs[2][16][NP];

    int tid = threadIdx.x;
    int tx = tid & 31;           // lane
    int ty = tid >> 5;           // warp 0..7
    int m0 = blockIdx.x * 64;
    int kbase = blockIdx.y * KCHUNK;

    int lm  = tid >> 2;          // A row within tile: 0..63
    int lk4 = (tid & 3) * 4;     // A k offset: 0,4,8,12
    int br  = tid >> 5;          // B row: 0..7 (and +8)
    int bc4 = (tid & 31) * 4;    // B col: 0..124

    const float* Arow = &A[(long long)(m0 + lm) * B_ + kbase + lk4];

    // prologue: stage 0 -> buffer 0
    {
        float4 v = *(const float4*)&Arow[0];
        As[0][lk4 + 0][lm] = v.x;
        As[0][lk4 + 1][lm] = v.y;
        As[0][lk4 + 2][lm] = v.z;
        As[0][lk4 + 3][lm] = v.w;
        *(float4*)&Bs[0][br][bc4]     = *(const float4*)&Bm[(kbase + br) * NP + bc4];
        *(float4*)&Bs[0][br + 8][bc4] = *(const float4*)&Bm[(kbase + br + 8) * NP + bc4];
    }
    __syncthreads();

    u64 acc2[4][4];              // [m-pair][n], pair = rows (2*i2, 2*i2+1)
    #pragma unroll
    for (int i = 0; i < 4; i++)
        #pragma unroll
        for (int j = 0; j < 4; j++) acc2[i][j] = 0ULL;

    const int T = KCHUNK / 16;   // 4 smem stages
    #pragma unroll
    for (int s = 0; s < T; s++) {
        // global prefetch for next smem stage
        float4 av, bv0, bv1;
        if (s + 1 < T) {
            int ko = (s + 1) * 16;
            av  = *(const float4*)&Arow[ko];
            bv0 = *(const float4*)&Bm[(kbase + ko + br) * NP + bc4];
            bv1 = *(const float4*)&Bm[(kbase + ko + br + 8) * NP + bc4];
        }
        int cb = s & 1;

        // ---- register-pipelined inner loop over 16 k ----
        ulonglong2 pa0 = *(const ulonglong2*)&As[cb][0][ty * 8];
        ulonglong2 pa1 = *(const ulonglong2*)&As[cb][0][ty * 8 + 4];
        float4     pb  = *(const float4*)&Bs[cb][0][tx * 4];
        #pragma unroll
        for (int k = 0; k < 16; k++) {
            ulonglong2 na0, na1;
            float4 nb;
            if (k < 15) {        // issue k+1 loads before k's math
                na0 = *(const ulonglong2*)&As[cb][k + 1][ty * 8];
                na1 = *(const ulonglong2*)&As[cb][k + 1][ty * 8 + 4];
                nb  = *(const float4*)&Bs[cb][k + 1][tx * 4];
            }
            u64 a2[4] = {pa0.x, pa0.y, pa1.x, pa1.y};
            u64 b2[4] = {pack2(pb.x), pack2(pb.y), pack2(pb.z), pack2(pb.w)};
            #pragma unroll
            for (int i = 0; i < 4; i++)
                #pragma unroll
                for (int j = 0; j < 4; j++)
                    fma2(acc2[i][j], a2[i], b2[j]);
            if (k < 15) { pa0 = na0; pa1 = na1; pb = nb; }
        }

        if (s + 1 < T) {
            int nb2 = cb ^ 1;
            As[nb2][lk4 + 0][lm] = av.x;
            As[nb2][lk4 + 1][lm] = av.y;
            As[nb2][lk4 + 2][lm] = av.z;
            As[nb2][lk4 + 3][lm] = av.w;
            *(float4*)&Bs[nb2][br][bc4]     = bv0;
            *(float4*)&Bs[nb2][br + 8][bc4] = bv1;
            __syncthreads();
        }
    }

    // unpack + write partials
    float* P = g_part + (long long)blockIdx.y * (B_ * NP);
    #pragma unroll
    for (int i2 = 0; i2 < 4; i2++) {
        float r0[4], r1[4];
        #pragma unroll
        for (int j = 0; j < 4; j++) unpack2(acc2[i2][j], r0[j], r1[j]);
        int m = m0 + ty * 8 + i2 * 2;
        *(float4*)&P[(m + 0) * NP + tx * 4] = make_float4(r0[0], r0[1], r0[2], r0[3]);
        *(float4*)&P[(m + 1) * NP + tx * 4] = make_float4(r1[0], r1[1], r1[2], r1[3]);
    }
}

// ---------------------------------------------------------------------------
// Kernel 3: reduce split-K partials into g_tmp (float4 vectorized)
// ---------------------------------------------------------------------------
__global__ void reduce_kernel() {
    int i = (blockIdx.x * 256 + threadIdx.x) * 4;   // 0 .. 131068
    float4 s = make_float4(0.f, 0.f, 0.f, 0.f);
    #pragma unroll
    for (int c = 0; c < KSPLIT; c++) {
        float4 v = *(const float4*)&g_part[c * (B_ * NP) + i];
        s.x += v.x; s.y += v.y; s.z += v.z; s.w += v.w;
    }
    *(float4*)&g_tmp[i] = s;
}

// ---------------------------------------------------------------------------
// Kernel 4: fused split-K reduce + SELU + L2 row-normalize -> out [1024,100]
// ---------------------------------------------------------------------------
__global__ void epilogue_kernel(float* __restrict__ out) {
    int b = blockIdx.x;
    int t = threadIdx.x;

    float s = 0.f;
    #pragma unroll
    for (int c = 0; c < KSPLIT; c++) s += g_part[c * (B_ * NP) + b * NP + t];

    const float kScale = 1.0507009873554804934193349852946f;
    const float kAlpha = 1.6732632423543772848170429916717f;
    float cv = kScale * (s > 0.f ? s : kAlpha * (expf(s) - 1.f));

    float v = (t < DIM_) ? cv * cv : 0.f;
    #pragma unroll
    for (int o = 16; o > 0; o >>= 1) v += __shfl_xor_sync(0xFFFFFFFFu, v, o);
    __shared__ float red[4];
    if ((t & 31) == 0) red[t >> 5] = v;
    __syncthreads();
    float nrm = rsqrtf(red[0] + red[1] + red[2] + red[3]);

    if (t < DIM_) out[b * DIM_ + t] = cv * nrm;
}

// ---------------------------------------------------------------------------
extern "C" void kernel_launch(void* const* d_in, const int* in_sizes, int n_in,
                              void* d_out, int out_size) {
    const float* emb   = (const float*)d_in[0];      // [50000,100] f32
    const int*   items = (const int*)d_in[1];        // [1024,200] int32
    const float* A     = (const float*)d_in[2];      // [1024,1024] f32
    const float* D     = (const float*)d_in[3];      // [1024,1024] f32
    const float* slen  = (const float*)d_in[4];      // [1024,1] f32
    float*       out   = (float*)d_out;              // [1024,100] f32

    gather_kernel<<<B_, 256>>>(emb, items, slen);

    dim3 ggrid(B_ / 64, KSPLIT);                  // (16,16) = 256 blocks
    gemm_splitk<<<ggrid, 256>>>(A, /*selB=*/0);   // partials of A @ rel
    reduce_kernel<<<(B_ * NP) / 1024, 256>>>();   // g_tmp = A @ rel
    gemm_splitk<<<ggrid, 256>>>(D, /*selB=*/1);   // partials of D @ (A @ rel)
    epilogue_kernel<<<B_, 128>>>(out);            // reduce + selu + L2 norm
}